// round 1
// baseline (speedup 1.0000x reference)
#include <cuda_runtime.h>
#include <cuda_bf16.h>
#include <math.h>

// Problem constants
#define S   512
#define B   128
#define D   300
#define H   512
#define H3  1536
#define V   50257

// ---------------- scratch (device globals: allocation-free) ----------------
__device__ float  g_xn[(size_t)B * S * D];     // normalized embeds, layout (b, s, d)
__device__ float  g_feats[S * B];              // feats, layout (s, b)
__device__ float4 g_wp4[(H / 4) * H3];         // W_hh interleaved: [kk4][g] -> w_hh[g][4kk4..+3]
__device__ float  g_ha[B * H];
__device__ float  g_hb[B * H];

// ---------------- kernel 0a: build interleaved W ----------------
__global__ void prep_w_kernel(const float* __restrict__ w_hh) {
    int idx = blockIdx.x * blockDim.x + threadIdx.x;   // total H3 * (H/4) = 196608
    if (idx >= H3 * (H / 4)) return;
    int g   = idx >> 7;        // / 128
    int kk4 = idx & 127;
    const float* src = w_hh + (size_t)g * H + kk4 * 4; // coalesced-ish reads along kk4
    float4 v;
    v.x = src[0]; v.y = src[1]; v.z = src[2]; v.w = src[3];
    g_wp4[kk4 * H3 + g] = v;
}

// ---------------- kernel 0b: zero initial hidden state ----------------
__global__ void zero_h_kernel() {
    int idx = blockIdx.x * blockDim.x + threadIdx.x;
    if (idx < B * H) g_ha[idx] = 0.0f;
}

// ---------------- kernel 1: gather + L2-normalize embeddings ----------------
// one warp per (s, b)
__global__ void gather_kernel(const int* __restrict__ ends,
                              const float* __restrict__ emb) {
    int w    = (blockIdx.x * blockDim.x + threadIdx.x) >> 5;
    int lane = threadIdx.x & 31;
    if (w >= S * B) return;
    int s = w >> 7;      // / B
    int b = w & 127;
    int vidx = ends[s * B + b];
    const float* row = emb + (size_t)vidx * D;

    float v[10];
    float ss = 0.0f;
#pragma unroll
    for (int i = 0; i < 10; ++i) {
        int d = lane + 32 * i;
        v[i] = (d < D) ? row[d] : 0.0f;
        ss += v[i] * v[i];
    }
#pragma unroll
    for (int m = 16; m; m >>= 1) ss += __shfl_xor_sync(0xffffffffu, ss, m);
    float inv = 1.0f / fmaxf(sqrtf(ss), 1e-8f);

    float* dst = g_xn + ((size_t)b * S + s) * D;
#pragma unroll
    for (int i = 0; i < 10; ++i) {
        int d = lane + 32 * i;
        if (d < D) dst[d] = v[i] * inv;
    }
}

// ---------------- kernel 2: causal max cosine-sim features ----------------
// grid (it=8, b=128); 256 threads; 64x64 C tile, 4x4 per thread; K chunks of 25
__global__ void feats_kernel() {
    const int it = blockIdx.x;
    const int b  = blockIdx.y;
    const float* Xb = g_xn + (size_t)b * S * D;

    const int tid = threadIdx.x;
    const int tx  = tid & 15;
    const int ty  = tid >> 4;

    __shared__ float As[64][25];
    __shared__ float Bs[64][25];

    const int i0 = it * 64;
    float rowmax[4] = { -INFINITY, -INFINITY, -INFINITY, -INFINITY };

    for (int jt = 0; jt <= it; ++jt) {
        const int j0 = jt * 64;
        float acc[4][4];
#pragma unroll
        for (int r = 0; r < 4; ++r)
#pragma unroll
            for (int c = 0; c < 4; ++c) acc[r][c] = 0.0f;

        for (int kc = 0; kc < 12; ++kc) {
            for (int l = tid; l < 1600; l += 256) {
                int row = l / 25, col = l - row * 25;
                As[row][col] = Xb[(size_t)(i0 + row) * D + kc * 25 + col];
                Bs[row][col] = Xb[(size_t)(j0 + row) * D + kc * 25 + col];
            }
            __syncthreads();
#pragma unroll
            for (int kk = 0; kk < 25; ++kk) {
                float a0 = As[ty * 4 + 0][kk];
                float a1 = As[ty * 4 + 1][kk];
                float a2 = As[ty * 4 + 2][kk];
                float a3 = As[ty * 4 + 3][kk];
                float c0 = Bs[tx * 4 + 0][kk];
                float c1 = Bs[tx * 4 + 1][kk];
                float c2 = Bs[tx * 4 + 2][kk];
                float c3 = Bs[tx * 4 + 3][kk];
                acc[0][0] += a0 * c0; acc[0][1] += a0 * c1; acc[0][2] += a0 * c2; acc[0][3] += a0 * c3;
                acc[1][0] += a1 * c0; acc[1][1] += a1 * c1; acc[1][2] += a1 * c2; acc[1][3] += a1 * c3;
                acc[2][0] += a2 * c0; acc[2][1] += a2 * c1; acc[2][2] += a2 * c2; acc[2][3] += a2 * c3;
                acc[3][0] += a3 * c0; acc[3][1] += a3 * c1; acc[3][2] += a3 * c2; acc[3][3] += a3 * c3;
            }
            __syncthreads();
        }
        // causal-masked running max
#pragma unroll
        for (int r = 0; r < 4; ++r) {
            int i = i0 + ty * 4 + r;
#pragma unroll
            for (int c = 0; c < 4; ++c) {
                int j = j0 + tx * 4 + c;
                if (j < i) rowmax[r] = fmaxf(rowmax[r], acc[r][c]);
            }
        }
    }
    // reduce over the 16 tx lanes (stays within each 16-lane half-warp)
#pragma unroll
    for (int m = 8; m; m >>= 1) {
#pragma unroll
        for (int r = 0; r < 4; ++r)
            rowmax[r] = fmaxf(rowmax[r], __shfl_xor_sync(0xffffffffu, rowmax[r], m));
    }
    if (tx == 0) {
#pragma unroll
        for (int r = 0; r < 4; ++r) {
            int i = i0 + ty * 4 + r;
            g_feats[i * B + b] = (i == 0) ? 0.0f : rowmax[r];
        }
    }
}

// ---------------- kernel 3: one GRU step ----------------
// grid (kt=16, bt=8); 256 threads: kl = tid%32 (gate dim), bg = tid/32 (batch pair)
__device__ __forceinline__ float sigmoidf_(float x) { return 1.0f / (1.0f + expf(-x)); }

__global__ void gru_step_kernel(int t,
                                const float* __restrict__ w_ih,
                                const float* __restrict__ b_ih,
                                const float* __restrict__ b_hh) {
    const float* __restrict__ hin  = (t & 1) ? g_hb : g_ha;
    float*       __restrict__ hout = (t & 1) ? g_ha : g_hb;

    const int kt = blockIdx.x;
    const int bt = blockIdx.y;
    const int tid = threadIdx.x;
    const int kl = tid & 31;
    const int bg = tid >> 5;           // 0..7
    const int k  = kt * 32 + kl;       // output hidden dim

    __shared__ float4 hs4[16 * 128];   // [bl][kk4], 32KB
    const float4* hin4 = (const float4*)hin;
    for (int idx = tid; idx < 16 * 128; idx += 256) {
        int bl = idx >> 7, kk4 = idx & 127;
        hs4[idx] = hin4[(size_t)(bt * 16 + bl) * 128 + kk4];
    }
    __syncthreads();

    float ar0 = 0.f, ar1 = 0.f, az0 = 0.f, az1 = 0.f, an0 = 0.f, an1 = 0.f;
    const float4* __restrict__ ha = hs4 + bg * 128;
    const float4* __restrict__ hb = hs4 + (bg + 8) * 128;

#pragma unroll 4
    for (int kk4 = 0; kk4 < 128; ++kk4) {
        const float4 wr = __ldg(&g_wp4[kk4 * H3 + k]);
        const float4 wz = __ldg(&g_wp4[kk4 * H3 + H + k]);
        const float4 wn = __ldg(&g_wp4[kk4 * H3 + 2 * H + k]);
        const float4 h0 = ha[kk4];
        const float4 h1 = hb[kk4];
        ar0 = fmaf(wr.x, h0.x, ar0); ar0 = fmaf(wr.y, h0.y, ar0);
        ar0 = fmaf(wr.z, h0.z, ar0); ar0 = fmaf(wr.w, h0.w, ar0);
        ar1 = fmaf(wr.x, h1.x, ar1); ar1 = fmaf(wr.y, h1.y, ar1);
        ar1 = fmaf(wr.z, h1.z, ar1); ar1 = fmaf(wr.w, h1.w, ar1);
        az0 = fmaf(wz.x, h0.x, az0); az0 = fmaf(wz.y, h0.y, az0);
        az0 = fmaf(wz.z, h0.z, az0); az0 = fmaf(wz.w, h0.w, az0);
        az1 = fmaf(wz.x, h1.x, az1); az1 = fmaf(wz.y, h1.y, az1);
        az1 = fmaf(wz.z, h1.z, az1); az1 = fmaf(wz.w, h1.w, az1);
        an0 = fmaf(wn.x, h0.x, an0); an0 = fmaf(wn.y, h0.y, an0);
        an0 = fmaf(wn.z, h0.z, an0); an0 = fmaf(wn.w, h0.w, an0);
        an1 = fmaf(wn.x, h1.x, an1); an1 = fmaf(wn.y, h1.y, an1);
        an1 = fmaf(wn.z, h1.z, an1); an1 = fmaf(wn.w, h1.w, an1);
    }

    const int b0 = bt * 16 + bg;
    const int b1 = b0 + 8;
    const float x0 = g_feats[t * B + b0];
    const float x1 = g_feats[t * B + b1];

    const float wir = w_ih[k],        bir = b_ih[k],        bhr = b_hh[k];
    const float wiz = w_ih[H + k],    biz = b_ih[H + k],    bhz = b_hh[H + k];
    const float win = w_ih[2 * H + k], bin = b_ih[2 * H + k], bhn = b_hh[2 * H + k];

    const float hold0 = ((const float*)hs4)[bg * 512 + k];
    const float hold1 = ((const float*)hs4)[(bg + 8) * 512 + k];

    float r0 = sigmoidf_(fmaf(x0, wir, bir) + ar0 + bhr);
    float z0 = sigmoidf_(fmaf(x0, wiz, biz) + az0 + bhz);
    float n0 = tanhf(fmaf(x0, win, bin) + r0 * (an0 + bhn));
    hout[(size_t)b0 * H + k] = (1.0f - z0) * n0 + z0 * hold0;

    float r1 = sigmoidf_(fmaf(x1, wir, bir) + ar1 + bhr);
    float z1 = sigmoidf_(fmaf(x1, wiz, biz) + az1 + bhz);
    float n1 = tanhf(fmaf(x1, win, bin) + r1 * (an1 + bhn));
    hout[(size_t)b1 * H + k] = (1.0f - z1) * n1 + z1 * hold1;
}

// ---------------- kernel 4: FC head ----------------
__global__ void final_kernel(const float* __restrict__ fcw,
                             const float* __restrict__ fcb,
                             float* __restrict__ out) {
    // after 512 steps (even count), h_last lives in g_ha
    const float* __restrict__ h = g_ha;
    int b = blockIdx.x;
    int tid = threadIdx.x;   // 128 threads
    float s = 0.0f;
#pragma unroll
    for (int d = tid; d < H; d += 128) s += h[(size_t)b * H + d] * fcw[d];
#pragma unroll
    for (int m = 16; m; m >>= 1) s += __shfl_xor_sync(0xffffffffu, s, m);
    __shared__ float ws[4];
    if ((tid & 31) == 0) ws[tid >> 5] = s;
    __syncthreads();
    if (tid == 0) out[b] = ws[0] + ws[1] + ws[2] + ws[3] + fcb[0];
}

// ---------------- launcher ----------------
// inputs (metadata order): 0 context(int32, unused), 1 ends(int32 SxB),
// 2 ends_ls(int32, unused), 3 embed_mat(f32 VxD), 4 w_ih(f32 3Hx1),
// 5 w_hh(f32 3HxH), 6 b_ih(f32 3H), 7 b_hh(f32 3H), 8 fc_w(f32 1xH), 9 fc_b(f32 1)
extern "C" void kernel_launch(void* const* d_in, const int* in_sizes, int n_in,
                              void* d_out, int out_size) {
    const int*   ends  = (const int*)  d_in[1];
    const float* emb   = (const float*)d_in[3];
    const float* w_ih  = (const float*)d_in[4];
    const float* w_hh  = (const float*)d_in[5];
    const float* b_ih  = (const float*)d_in[6];
    const float* b_hh  = (const float*)d_in[7];
    const float* fc_w  = (const float*)d_in[8];
    const float* fc_b  = (const float*)d_in[9];
    float* out = (float*)d_out;

    // 0: weight re-layout + h0 init
    prep_w_kernel<<<(H3 * (H / 4) + 255) / 256, 256>>>(w_hh);
    zero_h_kernel<<<(B * H + 1023) / 1024, 1024>>>();

    // 1: gather + normalize (one warp per (s,b))
    gather_kernel<<<(S * B) / 8, 256>>>(ends, emb);

    // 2: causal-max cosine features
    feats_kernel<<<dim3(8, 128), 256>>>();

    // 3: GRU recurrence, 512 sequential steps (ping-pong g_ha/g_hb)
    for (int t = 0; t < S; ++t) {
        gru_step_kernel<<<dim3(16, 8), 256>>>(t, w_ih, b_ih, b_hh);
    }

    // 4: FC head
    final_kernel<<<B, 128>>>(fc_w, fc_b, out);
}

// round 2
// speedup vs baseline: 2.2865x; 2.2865x over previous
#include <cuda_runtime.h>
#include <cuda_bf16.h>
#include <math.h>

// Problem constants
#define S   512
#define B   128
#define D   300
#define H   512
#define H3  1536
#define V   50257

#define NBLK 128            // persistent blocks (<=148 SMs, 1/SM)
#define NTHR 256

// ---------------- scratch (device globals: allocation-free) ----------------
__device__ float    g_xn[(size_t)B * S * D];   // normalized embeds, layout (b, s, d)
__device__ float    g_feats[S * B];            // feats, layout (s, b)
__device__ float    g_ha[H * B];               // hidden, DIM-MAJOR: h[d][b]
__device__ float    g_hb[H * B];
__device__ unsigned g_bar;                     // grid barrier counter

// ---------------- kernel 0: reset barrier counter (each graph replay) ------
__global__ void reset_bar_kernel() { g_bar = 0u; }

// ---------------- kernel 1: gather + L2-normalize embeddings ---------------
__global__ void gather_kernel(const int* __restrict__ ends,
                              const float* __restrict__ emb) {
    int w    = (blockIdx.x * blockDim.x + threadIdx.x) >> 5;
    int lane = threadIdx.x & 31;
    if (w >= S * B) return;
    int s = w >> 7;
    int b = w & 127;
    int vidx = ends[s * B + b];
    const float* row = emb + (size_t)vidx * D;

    float v[10];
    float ss = 0.0f;
#pragma unroll
    for (int i = 0; i < 10; ++i) {
        int d = lane + 32 * i;
        v[i] = (d < D) ? row[d] : 0.0f;
        ss += v[i] * v[i];
    }
#pragma unroll
    for (int m = 16; m; m >>= 1) ss += __shfl_xor_sync(0xffffffffu, ss, m);
    float inv = 1.0f / fmaxf(sqrtf(ss), 1e-8f);

    float* dst = g_xn + ((size_t)b * S + s) * D;
#pragma unroll
    for (int i = 0; i < 10; ++i) {
        int d = lane + 32 * i;
        if (d < D) dst[d] = v[i] * inv;
    }
}

// ---------------- kernel 2: causal max cosine-sim features -----------------
__global__ void feats_kernel() {
    const int it = blockIdx.x;
    const int b  = blockIdx.y;
    const float* Xb = g_xn + (size_t)b * S * D;

    const int tid = threadIdx.x;
    const int tx  = tid & 15;
    const int ty  = tid >> 4;

    __shared__ float As[64][25];
    __shared__ float Bs[64][25];

    const int i0 = it * 64;
    float rowmax[4] = { -INFINITY, -INFINITY, -INFINITY, -INFINITY };

    for (int jt = 0; jt <= it; ++jt) {
        const int j0 = jt * 64;
        float acc[4][4];
#pragma unroll
        for (int r = 0; r < 4; ++r)
#pragma unroll
            for (int c = 0; c < 4; ++c) acc[r][c] = 0.0f;

        for (int kc = 0; kc < 12; ++kc) {
            for (int l = tid; l < 1600; l += 256) {
                int row = l / 25, col = l - row * 25;
                As[row][col] = Xb[(size_t)(i0 + row) * D + kc * 25 + col];
                Bs[row][col] = Xb[(size_t)(j0 + row) * D + kc * 25 + col];
            }
            __syncthreads();
#pragma unroll
            for (int kk = 0; kk < 25; ++kk) {
                float a0 = As[ty * 4 + 0][kk];
                float a1 = As[ty * 4 + 1][kk];
                float a2 = As[ty * 4 + 2][kk];
                float a3 = As[ty * 4 + 3][kk];
                float c0 = Bs[tx * 4 + 0][kk];
                float c1 = Bs[tx * 4 + 1][kk];
                float c2 = Bs[tx * 4 + 2][kk];
                float c3 = Bs[tx * 4 + 3][kk];
                acc[0][0] += a0 * c0; acc[0][1] += a0 * c1; acc[0][2] += a0 * c2; acc[0][3] += a0 * c3;
                acc[1][0] += a1 * c0; acc[1][1] += a1 * c1; acc[1][2] += a1 * c2; acc[1][3] += a1 * c3;
                acc[2][0] += a2 * c0; acc[2][1] += a2 * c1; acc[2][2] += a2 * c2; acc[2][3] += a2 * c3;
                acc[3][0] += a3 * c0; acc[3][1] += a3 * c1; acc[3][2] += a3 * c2; acc[3][3] += a3 * c3;
            }
            __syncthreads();
        }
#pragma unroll
        for (int r = 0; r < 4; ++r) {
            int i = i0 + ty * 4 + r;
#pragma unroll
            for (int c = 0; c < 4; ++c) {
                int j = j0 + tx * 4 + c;
                if (j < i) rowmax[r] = fmaxf(rowmax[r], acc[r][c]);
            }
        }
    }
#pragma unroll
    for (int m = 8; m; m >>= 1) {
#pragma unroll
        for (int r = 0; r < 4; ++r)
            rowmax[r] = fmaxf(rowmax[r], __shfl_xor_sync(0xffffffffu, rowmax[r], m));
    }
    if (tx == 0) {
#pragma unroll
        for (int r = 0; r < 4; ++r) {
            int i = i0 + ty * 4 + r;
            g_feats[i * B + b] = (i == 0) ? 0.0f : rowmax[r];
        }
    }
}

// ---------------- kernel 3: persistent GRU over all 512 steps --------------
// grid = 128 blocks = 32 k-tiles (16 k each) x 4 b-tiles (32 batches each)
// smem: ws4[48][128] float4 (W slice, 98KB) + hs4[128][32] float4 (h tile, 64KB)
__device__ __forceinline__ float sigmoidf_(float x) { return 1.0f / (1.0f + expf(-x)); }

__global__ void __launch_bounds__(NTHR, 1)
gru_persist_kernel(const float* __restrict__ w_hh,
                   const float* __restrict__ w_ih,
                   const float* __restrict__ b_ih,
                   const float* __restrict__ b_hh) {
    extern __shared__ float4 smem[];
    float4* ws4 = smem;               // [ (kl*3+g) * 128 + kk4 ]
    float4* hs4 = smem + 48 * 128;    // [ kk4 * 32 + b_local ]

    const int tid  = threadIdx.x;
    const int lane = tid & 31;
    const int wid  = tid >> 5;            // 0..7
    const int kt   = blockIdx.x >> 2;     // 0..31
    const int bt   = blockIdx.x & 3;      // 0..3
    const int b    = bt * 32 + lane;      // this lane's batch

    // ---- load W slice into smem once (rows g*512 + kt*16 + kl, dims 512) ----
    for (int i = tid; i < 48 * 128; i += NTHR) {
        int row_l = i >> 7;               // kl*3 + g
        int kk4   = i & 127;
        int kl = row_l / 3, g = row_l - kl * 3;
        const float* src = w_hh + ((size_t)(g * H + kt * 16 + kl)) * H + kk4 * 4;
        ws4[i] = *(const float4*)src;
    }

    // ---- per-thread constants: 2 k-values, their scalar weights/biases ----
    const int k0l = wid * 2, k1l = wid * 2 + 1;
    const int k0g = kt * 16 + k0l, k1g = kt * 16 + k1l;
    const float wir0 = w_ih[k0g],       wiz0 = w_ih[H + k0g],     win0 = w_ih[2 * H + k0g];
    const float bir0 = b_ih[k0g],       biz0 = b_ih[H + k0g],     bin0 = b_ih[2 * H + k0g];
    const float bhr0 = b_hh[k0g],       bhz0 = b_hh[H + k0g],     bhn0 = b_hh[2 * H + k0g];
    const float wir1 = w_ih[k1g],       wiz1 = w_ih[H + k1g],     win1 = w_ih[2 * H + k1g];
    const float bir1 = b_ih[k1g],       biz1 = b_ih[H + k1g],     bin1 = b_ih[2 * H + k1g];
    const float bhr1 = b_hh[k1g],       bhz1 = b_hh[H + k1g],     bhn1 = b_hh[2 * H + k1g];

    const float4* __restrict__ pwr0 = ws4 + (k0l * 3 + 0) * 128;
    const float4* __restrict__ pwz0 = ws4 + (k0l * 3 + 1) * 128;
    const float4* __restrict__ pwn0 = ws4 + (k0l * 3 + 2) * 128;
    const float4* __restrict__ pwr1 = ws4 + (k1l * 3 + 0) * 128;
    const float4* __restrict__ pwz1 = ws4 + (k1l * 3 + 1) * 128;
    const float4* __restrict__ pwn1 = ws4 + (k1l * 3 + 2) * 128;

    __syncthreads();   // W ready

    for (int t = 0; t < S; ++t) {
        const float* h_in  = (t & 1) ? g_hb : g_ha;   // dim-major [d][b]
        float*       h_out = (t & 1) ? g_ha : g_hb;

        // ---- stage h tile into smem: hs4[kk4][b_local] ----
        if (t == 0) {
            float4 z = make_float4(0.f, 0.f, 0.f, 0.f);
            for (int i = tid; i < 128 * 32; i += NTHR) hs4[i] = z;
        } else {
            for (int i = tid; i < 128 * 32; i += NTHR) {
                int kk4 = i >> 5, bl = i & 31;
                int gb  = bt * 32 + bl;
                float4 v;
                v.x = __ldcg(&h_in[(kk4 * 4 + 0) * B + gb]);
                v.y = __ldcg(&h_in[(kk4 * 4 + 1) * B + gb]);
                v.z = __ldcg(&h_in[(kk4 * 4 + 2) * B + gb]);
                v.w = __ldcg(&h_in[(kk4 * 4 + 3) * B + gb]);
                hs4[i] = v;
            }
        }
        __syncthreads();

        // ---- accumulate gates: 2 k-values x 3 gates, reduce over 512 dims ----
        float ar0 = 0.f, az0 = 0.f, an0 = 0.f;
        float ar1 = 0.f, az1 = 0.f, an1 = 0.f;
#pragma unroll 4
        for (int kk4 = 0; kk4 < 128; ++kk4) {
            const float4 h = hs4[kk4 * 32 + lane];
            float4 w;
            w = pwr0[kk4];
            ar0 = fmaf(w.x, h.x, ar0); ar0 = fmaf(w.y, h.y, ar0);
            ar0 = fmaf(w.z, h.z, ar0); ar0 = fmaf(w.w, h.w, ar0);
            w = pwz0[kk4];
            az0 = fmaf(w.x, h.x, az0); az0 = fmaf(w.y, h.y, az0);
            az0 = fmaf(w.z, h.z, az0); az0 = fmaf(w.w, h.w, az0);
            w = pwn0[kk4];
            an0 = fmaf(w.x, h.x, an0); an0 = fmaf(w.y, h.y, an0);
            an0 = fmaf(w.z, h.z, an0); an0 = fmaf(w.w, h.w, an0);
            w = pwr1[kk4];
            ar1 = fmaf(w.x, h.x, ar1); ar1 = fmaf(w.y, h.y, ar1);
            ar1 = fmaf(w.z, h.z, ar1); ar1 = fmaf(w.w, h.w, ar1);
            w = pwz1[kk4];
            az1 = fmaf(w.x, h.x, az1); az1 = fmaf(w.y, h.y, az1);
            az1 = fmaf(w.z, h.z, az1); az1 = fmaf(w.w, h.w, az1);
            w = pwn1[kk4];
            an1 = fmaf(w.x, h.x, an1); an1 = fmaf(w.y, h.y, an1);
            an1 = fmaf(w.z, h.z, an1); an1 = fmaf(w.w, h.w, an1);
        }

        // ---- epilogue: gates, new h, store (coalesced: [k][b]) ----
        const float x = g_feats[t * B + b];
        const float* hsF = (const float*)hs4;
        const float hold0 = hsF[(k0g >> 2) * 128 + lane * 4 + (k0g & 3)];
        const float hold1 = hsF[(k1g >> 2) * 128 + lane * 4 + (k1g & 3)];

        float r0 = sigmoidf_(fmaf(x, wir0, bir0) + ar0 + bhr0);
        float z0 = sigmoidf_(fmaf(x, wiz0, biz0) + az0 + bhz0);
        float n0 = tanhf(fmaf(x, win0, bin0) + r0 * (an0 + bhn0));
        h_out[k0g * B + b] = (1.0f - z0) * n0 + z0 * hold0;

        float r1 = sigmoidf_(fmaf(x, wir1, bir1) + ar1 + bhr1);
        float z1 = sigmoidf_(fmaf(x, wiz1, biz1) + az1 + bhz1);
        float n1 = tanhf(fmaf(x, win1, bin1) + r1 * (an1 + bhn1));
        h_out[k1g * B + b] = (1.0f - z1) * n1 + z1 * hold1;

        // ---- grid barrier (monotonic counter; reset each replay) ----
        __threadfence();
        __syncthreads();
        if (tid == 0) {
            atomicAdd(&g_bar, 1u);
            const unsigned target = (unsigned)(t + 1) * (unsigned)NBLK;
            while (*((volatile unsigned*)&g_bar) < target) { }
        }
        __syncthreads();
    }
}

// ---------------- kernel 4: FC head (h is dim-major) -----------------------
__global__ void final_kernel(const float* __restrict__ fcw,
                             const float* __restrict__ fcb,
                             float* __restrict__ out) {
    const float* __restrict__ h = g_ha;   // 512 steps: last write lands in g_ha
    int b = threadIdx.x;                  // 128 threads, 1 block
    float s = 0.0f;
#pragma unroll 8
    for (int d = 0; d < H; ++d) s += h[d * B + b] * fcw[d];
    out[b] = s + fcb[0];
}

// ---------------- launcher ----------------
// inputs: 0 context(unused), 1 ends(SxB i32), 2 ends_ls(unused), 3 embed_mat,
// 4 w_ih, 5 w_hh, 6 b_ih, 7 b_hh, 8 fc_w, 9 fc_b
extern "C" void kernel_launch(void* const* d_in, const int* in_sizes, int n_in,
                              void* d_out, int out_size) {
    const int*   ends  = (const int*)  d_in[1];
    const float* emb   = (const float*)d_in[3];
    const float* w_ih  = (const float*)d_in[4];
    const float* w_hh  = (const float*)d_in[5];
    const float* b_ih  = (const float*)d_in[6];
    const float* b_hh  = (const float*)d_in[7];
    const float* fc_w  = (const float*)d_in[8];
    const float* fc_b  = (const float*)d_in[9];
    float* out = (float*)d_out;

    const int smem_bytes = (48 * 128 + 128 * 32) * sizeof(float4);  // 163840
    cudaFuncSetAttribute(gru_persist_kernel,
                         cudaFuncAttributeMaxDynamicSharedMemorySize, smem_bytes);

    reset_bar_kernel<<<1, 1>>>();
    gather_kernel<<<(S * B) / 8, 256>>>(ends, emb);
    feats_kernel<<<dim3(8, 128), 256>>>();
    gru_persist_kernel<<<NBLK, NTHR, smem_bytes>>>(w_hh, w_ih, b_ih, b_hh);
    final_kernel<<<1, B>>>(fc_w, fc_b, out);
}

// round 3
// speedup vs baseline: 2.2923x; 1.0025x over previous
#include <cuda_runtime.h>
#include <cuda_bf16.h>
#include <math.h>

// Problem constants
#define S   512
#define B   128
#define D   300
#define H   512
#define H3  1536
#define V   50257

#define NBLK 128            // persistent blocks (<=148 SMs, 1/SM)
#define NTHR 256

// ---------------- scratch (device globals: allocation-free) ----------------
__device__ float    g_xn[(size_t)B * S * D];   // normalized embeds, layout (b, s, d)
__device__ float    g_feats[S * B];            // feats, layout (s, b)
__device__ float    g_ha[H * B];               // hidden, DIM-MAJOR: h[d][b]
__device__ float    g_hb[H * B];
__device__ unsigned g_bar;                     // grid barrier counter

// ---------------- kernel 0: reset barrier counter (each graph replay) ------
__global__ void reset_bar_kernel() { g_bar = 0u; }

// ---------------- kernel 1: gather + L2-normalize embeddings ---------------
__global__ void gather_kernel(const int* __restrict__ ends,
                              const float* __restrict__ emb) {
    int w    = (blockIdx.x * blockDim.x + threadIdx.x) >> 5;
    int lane = threadIdx.x & 31;
    if (w >= S * B) return;
    int s = w >> 7;
    int b = w & 127;
    int vidx = ends[s * B + b];
    const float* row = emb + (size_t)vidx * D;

    float v[10];
    float ss = 0.0f;
#pragma unroll
    for (int i = 0; i < 10; ++i) {
        int d = lane + 32 * i;
        v[i] = (d < D) ? row[d] : 0.0f;
        ss += v[i] * v[i];
    }
#pragma unroll
    for (int m = 16; m; m >>= 1) ss += __shfl_xor_sync(0xffffffffu, ss, m);
    float inv = 1.0f / fmaxf(sqrtf(ss), 1e-8f);

    float* dst = g_xn + ((size_t)b * S + s) * D;
#pragma unroll
    for (int i = 0; i < 10; ++i) {
        int d = lane + 32 * i;
        if (d < D) dst[d] = v[i] * inv;
    }
}

// ---------------- kernel 2: causal max cosine-sim features -----------------
__global__ void feats_kernel() {
    const int it = blockIdx.x;
    const int b  = blockIdx.y;
    const float* Xb = g_xn + (size_t)b * S * D;

    const int tid = threadIdx.x;
    const int tx  = tid & 15;
    const int ty  = tid >> 4;

    __shared__ float As[64][25];
    __shared__ float Bs[64][25];

    const int i0 = it * 64;
    float rowmax[4] = { -INFINITY, -INFINITY, -INFINITY, -INFINITY };

    for (int jt = 0; jt <= it; ++jt) {
        const int j0 = jt * 64;
        float acc[4][4];
#pragma unroll
        for (int r = 0; r < 4; ++r)
#pragma unroll
            for (int c = 0; c < 4; ++c) acc[r][c] = 0.0f;

        for (int kc = 0; kc < 12; ++kc) {
            for (int l = tid; l < 1600; l += 256) {
                int row = l / 25, col = l - row * 25;
                As[row][col] = Xb[(size_t)(i0 + row) * D + kc * 25 + col];
                Bs[row][col] = Xb[(size_t)(j0 + row) * D + kc * 25 + col];
            }
            __syncthreads();
#pragma unroll
            for (int kk = 0; kk < 25; ++kk) {
                float a0 = As[ty * 4 + 0][kk];
                float a1 = As[ty * 4 + 1][kk];
                float a2 = As[ty * 4 + 2][kk];
                float a3 = As[ty * 4 + 3][kk];
                float c0 = Bs[tx * 4 + 0][kk];
                float c1 = Bs[tx * 4 + 1][kk];
                float c2 = Bs[tx * 4 + 2][kk];
                float c3 = Bs[tx * 4 + 3][kk];
                acc[0][0] += a0 * c0; acc[0][1] += a0 * c1; acc[0][2] += a0 * c2; acc[0][3] += a0 * c3;
                acc[1][0] += a1 * c0; acc[1][1] += a1 * c1; acc[1][2] += a1 * c2; acc[1][3] += a1 * c3;
                acc[2][0] += a2 * c0; acc[2][1] += a2 * c1; acc[2][2] += a2 * c2; acc[2][3] += a2 * c3;
                acc[3][0] += a3 * c0; acc[3][1] += a3 * c1; acc[3][2] += a3 * c2; acc[3][3] += a3 * c3;
            }
            __syncthreads();
        }
#pragma unroll
        for (int r = 0; r < 4; ++r) {
            int i = i0 + ty * 4 + r;
#pragma unroll
            for (int c = 0; c < 4; ++c) {
                int j = j0 + tx * 4 + c;
                if (j < i) rowmax[r] = fmaxf(rowmax[r], acc[r][c]);
            }
        }
    }
#pragma unroll
    for (int m = 8; m; m >>= 1) {
#pragma unroll
        for (int r = 0; r < 4; ++r)
            rowmax[r] = fmaxf(rowmax[r], __shfl_xor_sync(0xffffffffu, rowmax[r], m));
    }
    if (tx == 0) {
#pragma unroll
        for (int r = 0; r < 4; ++r) {
            int i = i0 + ty * 4 + r;
            g_feats[i * B + b] = (i == 0) ? 0.0f : rowmax[r];
        }
    }
}

// ---------------- kernel 3: persistent GRU over all 512 steps --------------
// grid = 128 blocks = 32 k-tiles (16 k each) x 4 b-tiles (32 batches each)
// smem: ws4[48][128] float4 (W slice, 98KB) + hs4[128][32] float4 (h tile, 64KB)
__device__ __forceinline__ float sigmoidf_(float x) { return 1.0f / (1.0f + expf(-x)); }

__global__ void __launch_bounds__(NTHR, 1)
gru_persist_kernel(const float* __restrict__ w_hh,
                   const float* __restrict__ w_ih,
                   const float* __restrict__ b_ih,
                   const float* __restrict__ b_hh) {
    extern __shared__ float4 smem[];
    float4* ws4 = smem;               // [ (kl*3+g) * 128 + kk4 ]
    float4* hs4 = smem + 48 * 128;    // [ kk4 * 32 + b_local ]

    const int tid  = threadIdx.x;
    const int lane = tid & 31;
    const int wid  = tid >> 5;            // 0..7
    const int kt   = blockIdx.x >> 2;     // 0..31
    const int bt   = blockIdx.x & 3;      // 0..3
    const int b    = bt * 32 + lane;      // this lane's batch

    // ---- load W slice into smem once (rows g*512 + kt*16 + kl, dims 512) ----
    for (int i = tid; i < 48 * 128; i += NTHR) {
        int row_l = i >> 7;               // kl*3 + g
        int kk4   = i & 127;
        int kl = row_l / 3, g = row_l - kl * 3;
        const float* src = w_hh + ((size_t)(g * H + kt * 16 + kl)) * H + kk4 * 4;
        ws4[i] = *(const float4*)src;
    }

    // ---- per-thread constants: 2 k-values, their scalar weights/biases ----
    const int k0l = wid * 2, k1l = wid * 2 + 1;
    const int k0g = kt * 16 + k0l, k1g = kt * 16 + k1l;
    const float wir0 = w_ih[k0g],       wiz0 = w_ih[H + k0g],     win0 = w_ih[2 * H + k0g];
    const float bir0 = b_ih[k0g],       biz0 = b_ih[H + k0g],     bin0 = b_ih[2 * H + k0g];
    const float bhr0 = b_hh[k0g],       bhz0 = b_hh[H + k0g],     bhn0 = b_hh[2 * H + k0g];
    const float wir1 = w_ih[k1g],       wiz1 = w_ih[H + k1g],     win1 = w_ih[2 * H + k1g];
    const float bir1 = b_ih[k1g],       biz1 = b_ih[H + k1g],     bin1 = b_ih[2 * H + k1g];
    const float bhr1 = b_hh[k1g],       bhz1 = b_hh[H + k1g],     bhn1 = b_hh[2 * H + k1g];

    const float4* __restrict__ pwr0 = ws4 + (k0l * 3 + 0) * 128;
    const float4* __restrict__ pwz0 = ws4 + (k0l * 3 + 1) * 128;
    const float4* __restrict__ pwn0 = ws4 + (k0l * 3 + 2) * 128;
    const float4* __restrict__ pwr1 = ws4 + (k1l * 3 + 0) * 128;
    const float4* __restrict__ pwz1 = ws4 + (k1l * 3 + 1) * 128;
    const float4* __restrict__ pwn1 = ws4 + (k1l * 3 + 2) * 128;

    __syncthreads();   // W ready

    for (int t = 0; t < S; ++t) {
        const float* h_in  = (t & 1) ? g_hb : g_ha;   // dim-major [d][b]
        float*       h_out = (t & 1) ? g_ha : g_hb;

        // ---- stage h tile into smem: hs4[kk4][b_local] ----
        if (t == 0) {
            float4 z = make_float4(0.f, 0.f, 0.f, 0.f);
            for (int i = tid; i < 128 * 32; i += NTHR) hs4[i] = z;
        } else {
            for (int i = tid; i < 128 * 32; i += NTHR) {
                int kk4 = i >> 5, bl = i & 31;
                int gb  = bt * 32 + bl;
                float4 v;
                v.x = __ldcg(&h_in[(kk4 * 4 + 0) * B + gb]);
                v.y = __ldcg(&h_in[(kk4 * 4 + 1) * B + gb]);
                v.z = __ldcg(&h_in[(kk4 * 4 + 2) * B + gb]);
                v.w = __ldcg(&h_in[(kk4 * 4 + 3) * B + gb]);
                hs4[i] = v;
            }
        }
        __syncthreads();

        // ---- accumulate gates: 2 k-values x 3 gates, reduce over 512 dims ----
        float ar0 = 0.f, az0 = 0.f, an0 = 0.f;
        float ar1 = 0.f, az1 = 0.f, an1 = 0.f;
#pragma unroll 4
        for (int kk4 = 0; kk4 < 128; ++kk4) {
            const float4 h = hs4[kk4 * 32 + lane];
            float4 w;
            w = pwr0[kk4];
            ar0 = fmaf(w.x, h.x, ar0); ar0 = fmaf(w.y, h.y, ar0);
            ar0 = fmaf(w.z, h.z, ar0); ar0 = fmaf(w.w, h.w, ar0);
            w = pwz0[kk4];
            az0 = fmaf(w.x, h.x, az0); az0 = fmaf(w.y, h.y, az0);
            az0 = fmaf(w.z, h.z, az0); az0 = fmaf(w.w, h.w, az0);
            w = pwn0[kk4];
            an0 = fmaf(w.x, h.x, an0); an0 = fmaf(w.y, h.y, an0);
            an0 = fmaf(w.z, h.z, an0); an0 = fmaf(w.w, h.w, an0);
            w = pwr1[kk4];
            ar1 = fmaf(w.x, h.x, ar1); ar1 = fmaf(w.y, h.y, ar1);
            ar1 = fmaf(w.z, h.z, ar1); ar1 = fmaf(w.w, h.w, ar1);
            w = pwz1[kk4];
            az1 = fmaf(w.x, h.x, az1); az1 = fmaf(w.y, h.y, az1);
            az1 = fmaf(w.z, h.z, az1); az1 = fmaf(w.w, h.w, az1);
            w = pwn1[kk4];
            an1 = fmaf(w.x, h.x, an1); an1 = fmaf(w.y, h.y, an1);
            an1 = fmaf(w.z, h.z, an1); an1 = fmaf(w.w, h.w, an1);
        }

        // ---- epilogue: gates, new h, store (coalesced: [k][b]) ----
        const float x = g_feats[t * B + b];
        const float* hsF = (const float*)hs4;
        const float hold0 = hsF[(k0g >> 2) * 128 + lane * 4 + (k0g & 3)];
        const float hold1 = hsF[(k1g >> 2) * 128 + lane * 4 + (k1g & 3)];

        float r0 = sigmoidf_(fmaf(x, wir0, bir0) + ar0 + bhr0);
        float z0 = sigmoidf_(fmaf(x, wiz0, biz0) + az0 + bhz0);
        float n0 = tanhf(fmaf(x, win0, bin0) + r0 * (an0 + bhn0));
        h_out[k0g * B + b] = (1.0f - z0) * n0 + z0 * hold0;

        float r1 = sigmoidf_(fmaf(x, wir1, bir1) + ar1 + bhr1);
        float z1 = sigmoidf_(fmaf(x, wiz1, biz1) + az1 + bhz1);
        float n1 = tanhf(fmaf(x, win1, bin1) + r1 * (an1 + bhn1));
        h_out[k1g * B + b] = (1.0f - z1) * n1 + z1 * hold1;

        // ---- grid barrier (monotonic counter; reset each replay) ----
        __threadfence();
        __syncthreads();
        if (tid == 0) {
            atomicAdd(&g_bar, 1u);
            const unsigned target = (unsigned)(t + 1) * (unsigned)NBLK;
            while (*((volatile unsigned*)&g_bar) < target) { }
        }
        __syncthreads();
    }
}

// ---------------- kernel 4: FC head (h is dim-major) -----------------------
__global__ void final_kernel(const float* __restrict__ fcw,
                             const float* __restrict__ fcb,
                             float* __restrict__ out) {
    const float* __restrict__ h = g_ha;   // 512 steps: last write lands in g_ha
    int b = threadIdx.x;                  // 128 threads, 1 block
    float s = 0.0f;
#pragma unroll 8
    for (int d = 0; d < H; ++d) s += h[d * B + b] * fcw[d];
    out[b] = s + fcb[0];
}

// ---------------- launcher ----------------
// inputs: 0 context(unused), 1 ends(SxB i32), 2 ends_ls(unused), 3 embed_mat,
// 4 w_ih, 5 w_hh, 6 b_ih, 7 b_hh, 8 fc_w, 9 fc_b
extern "C" void kernel_launch(void* const* d_in, const int* in_sizes, int n_in,
                              void* d_out, int out_size) {
    const int*   ends  = (const int*)  d_in[1];
    const float* emb   = (const float*)d_in[3];
    const float* w_ih  = (const float*)d_in[4];
    const float* w_hh  = (const float*)d_in[5];
    const float* b_ih  = (const float*)d_in[6];
    const float* b_hh  = (const float*)d_in[7];
    const float* fc_w  = (const float*)d_in[8];
    const float* fc_b  = (const float*)d_in[9];
    float* out = (float*)d_out;

    const int smem_bytes = (48 * 128 + 128 * 32) * sizeof(float4);  // 163840
    cudaFuncSetAttribute(gru_persist_kernel,
                         cudaFuncAttributeMaxDynamicSharedMemorySize, smem_bytes);

    reset_bar_kernel<<<1, 1>>>();
    gather_kernel<<<(S * B) / 8, 256>>>(ends, emb);
    feats_kernel<<<dim3(8, 128), 256>>>();
    gru_persist_kernel<<<NBLK, NTHR, smem_bytes>>>(w_hh, w_ih, b_ih, b_hh);
    final_kernel<<<1, B>>>(fc_w, fc_b, out);
}

// round 4
// speedup vs baseline: 3.1754x; 1.3853x over previous
#include <cuda_runtime.h>
#include <cuda_bf16.h>
#include <math.h>

#define S   512
#define B   128
#define D   300
#define H   512
#define V   50257
#define NBLK 128
#define GNT  256   // GRU threads (8 warps)

// ---------------- device scratch ----------------
__device__ float    g_xn[(size_t)B * S * D];
__device__ float    g_feats[S * B];     // (s, b)
__device__ float    g_ha[H * B];        // dim-major h[d][b]
__device__ float    g_hb[H * B];
__device__ unsigned g_bar;

__global__ void reset_bar_kernel() { g_bar = 0u; }
__global__ void zero_h_kernel() {
    int i = blockIdx.x * blockDim.x + threadIdx.x;
    if (i < H * B) g_ha[i] = 0.0f;
}

// ---------------- helpers ----------------
__device__ __forceinline__ void ffma2(unsigned long long& a,
                                      unsigned long long w,
                                      unsigned long long h) {
    asm("fma.rn.f32x2 %0, %1, %2, %0;" : "+l"(a) : "l"(w), "l"(h));
}
__device__ __forceinline__ unsigned long long dup2(float v) {
    unsigned long long r; unsigned u = __float_as_uint(v);
    asm("mov.b64 %0, {%1, %1};" : "=l"(r) : "r"(u));
    return r;
}
__device__ __forceinline__ float sigmoidf_(float x) { return 1.0f / (1.0f + expf(-x)); }

// ---------------- kernel 1: gather + normalize ----------------
__global__ void gather_kernel(const int* __restrict__ ends,
                              const float* __restrict__ emb) {
    int w    = (blockIdx.x * blockDim.x + threadIdx.x) >> 5;
    int lane = threadIdx.x & 31;
    if (w >= S * B) return;
    int s = w >> 7, b = w & 127;
    const float* row = emb + (size_t)ends[s * B + b] * D;
    float v[10]; float ss = 0.0f;
#pragma unroll
    for (int i = 0; i < 10; ++i) {
        int d = lane + 32 * i;
        v[i] = (d < D) ? row[d] : 0.0f;
        ss += v[i] * v[i];
    }
#pragma unroll
    for (int m = 16; m; m >>= 1) ss += __shfl_xor_sync(0xffffffffu, ss, m);
    float inv = 1.0f / fmaxf(sqrtf(ss), 1e-8f);
    float* dst = g_xn + ((size_t)b * S + s) * D;
#pragma unroll
    for (int i = 0; i < 10; ++i) {
        int d = lane + 32 * i;
        if (d < D) dst[d] = v[i] * inv;
    }
}

// ---------------- kernel 2: causal max cosine sims ----------------
__global__ void feats_kernel() {
    const int it = blockIdx.x, b = blockIdx.y;
    const float* Xb = g_xn + (size_t)b * S * D;
    const int tid = threadIdx.x, tx = tid & 15, ty = tid >> 4;
    __shared__ float As[64][25];
    __shared__ float Bs[64][25];
    const int i0 = it * 64;
    float rowmax[4] = { -INFINITY, -INFINITY, -INFINITY, -INFINITY };

    for (int jt = 0; jt <= it; ++jt) {
        const int j0 = jt * 64;
        float acc[4][4];
#pragma unroll
        for (int r = 0; r < 4; ++r)
#pragma unroll
            for (int c = 0; c < 4; ++c) acc[r][c] = 0.0f;
        for (int kc = 0; kc < 12; ++kc) {
            for (int l = tid; l < 1600; l += 256) {
                int row = l / 25, col = l - row * 25;
                As[row][col] = Xb[(size_t)(i0 + row) * D + kc * 25 + col];
                Bs[row][col] = Xb[(size_t)(j0 + row) * D + kc * 25 + col];
            }
            __syncthreads();
#pragma unroll
            for (int kk = 0; kk < 25; ++kk) {
                float a0 = As[ty*4+0][kk], a1 = As[ty*4+1][kk];
                float a2 = As[ty*4+2][kk], a3 = As[ty*4+3][kk];
                float c0 = Bs[tx*4+0][kk], c1 = Bs[tx*4+1][kk];
                float c2 = Bs[tx*4+2][kk], c3 = Bs[tx*4+3][kk];
                acc[0][0]+=a0*c0; acc[0][1]+=a0*c1; acc[0][2]+=a0*c2; acc[0][3]+=a0*c3;
                acc[1][0]+=a1*c0; acc[1][1]+=a1*c1; acc[1][2]+=a1*c2; acc[1][3]+=a1*c3;
                acc[2][0]+=a2*c0; acc[2][1]+=a2*c1; acc[2][2]+=a2*c2; acc[2][3]+=a2*c3;
                acc[3][0]+=a3*c0; acc[3][1]+=a3*c1; acc[3][2]+=a3*c2; acc[3][3]+=a3*c3;
            }
            __syncthreads();
        }
#pragma unroll
        for (int r = 0; r < 4; ++r) {
            int i = i0 + ty * 4 + r;
#pragma unroll
            for (int c = 0; c < 4; ++c) {
                int j = j0 + tx * 4 + c;
                if (j < i) rowmax[r] = fmaxf(rowmax[r], acc[r][c]);
            }
        }
    }
#pragma unroll
    for (int m = 8; m; m >>= 1)
#pragma unroll
        for (int r = 0; r < 4; ++r)
            rowmax[r] = fmaxf(rowmax[r], __shfl_xor_sync(0xffffffffu, rowmax[r], m));
    if (tx == 0)
#pragma unroll
        for (int r = 0; r < 4; ++r) {
            int i = i0 + ty * 4 + r;
            g_feats[i * B + b] = (i == 0) ? 0.0f : rowmax[r];
        }
}

// ---------------- kernel 3: persistent GRU ----------------
// block = 8 k (kt=blockIdx>>1) x 64 b (bt=blockIdx&1); 8 warps split 512 dims.
// lane owns batch pair b0 = bt*64 + 2*lane. acc: f32x2 over k-pairs.
// smem: W pairs ws64[512][16] (64KB) + partials part[8][3][4][2][32] u64 (48KB)
#define WS_U64   (512 * 16)
#define PART_U64 (8 * 3 * 4 * 2 * 32)
#define GRU_SMEM ((WS_U64 + PART_U64) * 8)

__global__ void __launch_bounds__(GNT, 1)
gru_persist_kernel(const float* __restrict__ w_hh,
                   const float* __restrict__ w_ih,
                   const float* __restrict__ b_ih,
                   const float* __restrict__ b_hh) {
    extern __shared__ unsigned long long sm64[];
    unsigned long long* ws64 = sm64;            // [d*16 + g*4 + kp]
    unsigned long long* part = sm64 + WS_U64;
    float* partf = (float*)part;

    const int tid  = threadIdx.x;
    const int lane = tid & 31;
    const int w    = tid >> 5;           // warp 0..7, dims [w*64, w*64+64)
    const int kt   = blockIdx.x >> 1;
    const int bt   = blockIdx.x & 1;
    const int bb0  = bt * 64 + 2 * lane; // compute lanes' batch pair

    // ---- one-time: pack W into k-pair-interleaved smem ----
    for (int i = tid; i < 12 * 512; i += GNT) {
        int gk = i >> 9, d = i & 511;        // gk = g*4 + kp
        int g = gk >> 2, kp = gk & 3;
        int k0 = kt * 8 + kp * 2;
        float lo = w_hh[((size_t)(g * H + k0)) * H + d];
        float hi = w_hh[((size_t)(g * H + k0 + 1)) * H + d];
        unsigned long long v;
        asm("mov.b64 %0, {%1, %2};" : "=l"(v)
            : "r"(__float_as_uint(lo)), "r"(__float_as_uint(hi)));
        ws64[d * 16 + gk] = v;
    }

    // ---- per-thread epilogue constants (thread owns k = kt*8 + (tid>>5), 2 b) ----
    const int kl   = tid >> 5;           // 0..7
    const int kg   = kt * 8 + kl;
    const int eb0  = bt * 64 + 2 * (tid & 31);
    const float wir = w_ih[kg],       wiz = w_ih[H + kg],     win = w_ih[2*H + kg];
    const float brr = b_ih[kg] + b_hh[kg];
    const float bzz = b_ih[H + kg] + b_hh[H + kg];
    const float bin = b_ih[2*H + kg], bhn = b_hh[2*H + kg];
    const int   kp_e = kl >> 1, half_e = kl & 1;

    __syncthreads();

    for (int t = 0; t < S; ++t) {
        const float* __restrict__ h_in  = (t & 1) ? g_hb : g_ha;
        float*       __restrict__ h_out = (t & 1) ? g_ha : g_hb;

        // ---- accumulate partials over this warp's 64 dims ----
        unsigned long long acc[3][4][2];
#pragma unroll
        for (int g = 0; g < 3; ++g)
#pragma unroll
            for (int kp = 0; kp < 4; ++kp) { acc[g][kp][0] = 0ull; acc[g][kp][1] = 0ull; }

#pragma unroll 4
        for (int dl = 0; dl < 64; ++dl) {
            const int d = w * 64 + dl;
            const float2 hv = __ldcg((const float2*)&h_in[(size_t)d * B + bb0]);
            const unsigned long long h0 = dup2(hv.x);
            const unsigned long long h1 = dup2(hv.y);
            const ulonglong2* wp = (const ulonglong2*)(ws64 + d * 16);
#pragma unroll
            for (int e = 0; e < 6; ++e) {
                ulonglong2 wv = wp[e];
                int g = e >> 1, kp = (e & 1) * 2;
                ffma2(acc[g][kp][0],     wv.x, h0);
                ffma2(acc[g][kp][1],     wv.x, h1);
                ffma2(acc[g][kp + 1][0], wv.y, h0);
                ffma2(acc[g][kp + 1][1], wv.y, h1);
            }
        }

        // ---- store partials, reduce across 8 warps ----
#pragma unroll
        for (int g = 0; g < 3; ++g)
#pragma unroll
            for (int kp = 0; kp < 4; ++kp)
#pragma unroll
                for (int bj = 0; bj < 2; ++bj)
                    part[(((w * 3 + g) * 4 + kp) * 2 + bj) * 32 + lane] = acc[g][kp][bj];
        __syncthreads();

        float ga[3][2];   // [gate][bj]
#pragma unroll
        for (int g = 0; g < 3; ++g)
#pragma unroll
            for (int bj = 0; bj < 2; ++bj) {
                float s = 0.0f;
#pragma unroll
                for (int ww = 0; ww < 8; ++ww)
                    s += partf[((((ww * 3 + g) * 4 + kp_e) * 2 + bj) * 32 + (tid & 31)) * 2 + half_e];
                ga[g][bj] = s;
            }

        // ---- epilogue: gates + store h_out[k][b0..b1] ----
        const float2 xv   = __ldcg((const float2*)&g_feats[t * B + eb0]);
        const float2 hold = __ldcg((const float2*)&h_in[(size_t)kg * B + eb0]);
        float2 o;
        {
            float r = sigmoidf_(fmaf(xv.x, wir, brr) + ga[0][0]);
            float z = sigmoidf_(fmaf(xv.x, wiz, bzz) + ga[1][0]);
            float n = tanhf(fmaf(xv.x, win, bin) + r * (ga[2][0] + bhn));
            o.x = (1.0f - z) * n + z * hold.x;
        }
        {
            float r = sigmoidf_(fmaf(xv.y, wir, brr) + ga[0][1]);
            float z = sigmoidf_(fmaf(xv.y, wiz, bzz) + ga[1][1]);
            float n = tanhf(fmaf(xv.y, win, bin) + r * (ga[2][1] + bhn));
            o.y = (1.0f - z) * n + z * hold.y;
        }
        *(float2*)&h_out[(size_t)kg * B + eb0] = o;

        // ---- grid barrier (skip after last step) ----
        if (t < S - 1) {
            __threadfence();
            __syncthreads();
            if (tid == 0) {
                atomicAdd(&g_bar, 1u);
                const unsigned target = (unsigned)(t + 1) * (unsigned)NBLK;
                while (*((volatile unsigned*)&g_bar) < target) { }
            }
            __syncthreads();
        }
    }
}

// ---------------- kernel 4: FC head ----------------
__global__ void final_kernel(const float* __restrict__ fcw,
                             const float* __restrict__ fcb,
                             float* __restrict__ out) {
    const float* __restrict__ h = g_ha;   // 512 steps -> last write in g_ha
    int b = threadIdx.x;
    float s = 0.0f;
#pragma unroll 8
    for (int d = 0; d < H; ++d) s += h[d * B + b] * fcw[d];
    out[b] = s + fcb[0];
}

// ---------------- launcher ----------------
extern "C" void kernel_launch(void* const* d_in, const int* in_sizes, int n_in,
                              void* d_out, int out_size) {
    const int*   ends = (const int*)  d_in[1];
    const float* emb  = (const float*)d_in[3];
    const float* w_ih = (const float*)d_in[4];
    const float* w_hh = (const float*)d_in[5];
    const float* b_ih = (const float*)d_in[6];
    const float* b_hh = (const float*)d_in[7];
    const float* fc_w = (const float*)d_in[8];
    const float* fc_b = (const float*)d_in[9];
    float* out = (float*)d_out;

    cudaFuncSetAttribute(gru_persist_kernel,
                         cudaFuncAttributeMaxDynamicSharedMemorySize, GRU_SMEM);

    reset_bar_kernel<<<1, 1>>>();
    zero_h_kernel<<<(H * B + 1023) / 1024, 1024>>>();
    gather_kernel<<<(S * B) / 8, 256>>>(ends, emb);
    feats_kernel<<<dim3(8, 128), 256>>>();
    gru_persist_kernel<<<NBLK, GNT, GRU_SMEM>>>(w_hh, w_ih, b_ih, b_hh);
    final_kernel<<<1, B>>>(fc_w, fc_b, out);
}

// round 5
// speedup vs baseline: 4.2110x; 1.3262x over previous
#include <cuda_runtime.h>
#include <cuda_bf16.h>
#include <math.h>

#define S   512
#define B   128
#define D   300
#define H   512
#define V   50257
#define NBLK 128
#define GNT  256   // GRU threads (8 warps)

// ---------------- device scratch ----------------
__device__ float    g_xn[(size_t)B * S * D];
__device__ float    g_feats[S * B];     // (s, b)
__device__ float    g_ha[H * B];        // dim-major h[d][b]
__device__ float    g_hb[H * B];
__device__ unsigned g_bar2[64];         // [0]: bt=0, [32]: bt=1 (separate lines)

__global__ void reset_bar_kernel() { g_bar2[0] = 0u; g_bar2[32] = 0u; }
__global__ void zero_h_kernel() {
    int i = blockIdx.x * blockDim.x + threadIdx.x;
    if (i < H * B) g_ha[i] = 0.0f;
}

// ---------------- helpers ----------------
__device__ __forceinline__ void ffma2(unsigned long long& a,
                                      unsigned long long w,
                                      unsigned long long h) {
    asm("fma.rn.f32x2 %0, %1, %2, %0;" : "+l"(a) : "l"(w), "l"(h));
}
__device__ __forceinline__ unsigned long long dup2(float v) {
    unsigned long long r; unsigned u = __float_as_uint(v);
    asm("mov.b64 %0, {%1, %1};" : "=l"(r) : "r"(u));
    return r;
}
__device__ __forceinline__ float2 unpk(unsigned long long v) {
    unsigned lo, hi;
    asm("mov.b64 {%0, %1}, %2;" : "=r"(lo), "=r"(hi) : "l"(v));
    return make_float2(__uint_as_float(lo), __uint_as_float(hi));
}
__device__ __forceinline__ float sigmoidf_(float x) { return 1.0f / (1.0f + expf(-x)); }

// ---------------- kernel 1: gather + normalize ----------------
__global__ void gather_kernel(const int* __restrict__ ends,
                              const float* __restrict__ emb) {
    int w    = (blockIdx.x * blockDim.x + threadIdx.x) >> 5;
    int lane = threadIdx.x & 31;
    if (w >= S * B) return;
    int s = w >> 7, b = w & 127;
    const float* row = emb + (size_t)ends[s * B + b] * D;
    float v[10]; float ss = 0.0f;
#pragma unroll
    for (int i = 0; i < 10; ++i) {
        int d = lane + 32 * i;
        v[i] = (d < D) ? row[d] : 0.0f;
        ss += v[i] * v[i];
    }
#pragma unroll
    for (int m = 16; m; m >>= 1) ss += __shfl_xor_sync(0xffffffffu, ss, m);
    float inv = 1.0f / fmaxf(sqrtf(ss), 1e-8f);
    float* dst = g_xn + ((size_t)b * S + s) * D;
#pragma unroll
    for (int i = 0; i < 10; ++i) {
        int d = lane + 32 * i;
        if (d < D) dst[d] = v[i] * inv;
    }
}

// ---------------- kernel 2: causal max cosine sims (transposed + f32x2) ----
// smem tiles transposed: At[kk][row], pad 68 -> LDS.128 reads, FFMA2 compute
#define FP 68
__global__ void feats_kernel() {
    const int it = blockIdx.x, b = blockIdx.y;
    const float* Xb = g_xn + (size_t)b * S * D;
    const int tid = threadIdx.x, tx = tid & 15, ty = tid >> 4;
    const int wa = tid >> 5, lane = tid & 31;

    __shared__ __align__(16) float At[25 * FP];
    __shared__ __align__(16) float Bt[25 * FP];

    const int i0 = it * 64;
    float rowmax[4] = { -INFINITY, -INFINITY, -INFINITY, -INFINITY };

    for (int jt = 0; jt <= it; ++jt) {
        const int j0 = jt * 64;
        unsigned long long acc2[4][2];
#pragma unroll
        for (int r = 0; r < 4; ++r) { acc2[r][0] = 0ull; acc2[r][1] = 0ull; }

        for (int kc = 0; kc < 12; ++kc) {
            __syncthreads();
            if (lane < 25) {
#pragma unroll
                for (int i = 0; i < 8; ++i) {
                    int row = wa * 8 + i;
                    At[lane * FP + row] = Xb[(size_t)(i0 + row) * D + kc * 25 + lane];
                    Bt[lane * FP + row] = Xb[(size_t)(j0 + row) * D + kc * 25 + lane];
                }
            }
            __syncthreads();
#pragma unroll
            for (int kk = 0; kk < 25; ++kk) {
                const float4 a4 = *(const float4*)(At + kk * FP + ty * 4);
                const ulonglong2 cp = *(const ulonglong2*)(Bt + kk * FP + tx * 4);
                const unsigned long long a0 = dup2(a4.x), a1 = dup2(a4.y);
                const unsigned long long a2 = dup2(a4.z), a3 = dup2(a4.w);
                ffma2(acc2[0][0], a0, cp.x); ffma2(acc2[0][1], a0, cp.y);
                ffma2(acc2[1][0], a1, cp.x); ffma2(acc2[1][1], a1, cp.y);
                ffma2(acc2[2][0], a2, cp.x); ffma2(acc2[2][1], a2, cp.y);
                ffma2(acc2[3][0], a3, cp.x); ffma2(acc2[3][1], a3, cp.y);
            }
        }
        // causal-masked running max
#pragma unroll
        for (int r = 0; r < 4; ++r) {
            int i = i0 + ty * 4 + r;
            float2 v01 = unpk(acc2[r][0]);
            float2 v23 = unpk(acc2[r][1]);
            int j = j0 + tx * 4;
            if (j + 0 < i) rowmax[r] = fmaxf(rowmax[r], v01.x);
            if (j + 1 < i) rowmax[r] = fmaxf(rowmax[r], v01.y);
            if (j + 2 < i) rowmax[r] = fmaxf(rowmax[r], v23.x);
            if (j + 3 < i) rowmax[r] = fmaxf(rowmax[r], v23.y);
        }
    }
#pragma unroll
    for (int m = 8; m; m >>= 1)
#pragma unroll
        for (int r = 0; r < 4; ++r)
            rowmax[r] = fmaxf(rowmax[r], __shfl_xor_sync(0xffffffffu, rowmax[r], m));
    if (tx == 0)
#pragma unroll
        for (int r = 0; r < 4; ++r) {
            int i = i0 + ty * 4 + r;
            g_feats[i * B + b] = (i == 0) ? 0.0f : rowmax[r];
        }
}

// ---------------- kernel 3: persistent GRU ----------------
// block = 8 k (kt) x 64 b (bt); 8 warps split 512 dims; f32x2 accumulate;
// h loads software-pipelined (chunks of 8 dims); per-bt grid barrier.
#define WS_U64   (512 * 16)
#define PART_U64 (8 * 3 * 4 * 2 * 32)
#define GRU_SMEM ((WS_U64 + PART_U64) * 8)

__global__ void __launch_bounds__(GNT, 1)
gru_persist_kernel(const float* __restrict__ w_hh,
                   const float* __restrict__ w_ih,
                   const float* __restrict__ b_ih,
                   const float* __restrict__ b_hh) {
    extern __shared__ unsigned long long sm64[];
    unsigned long long* ws64 = sm64;            // [d*16 + g*4 + kp]
    unsigned long long* part = sm64 + WS_U64;
    float* partf = (float*)part;

    const int tid  = threadIdx.x;
    const int lane = tid & 31;
    const int w    = tid >> 5;           // warp 0..7 owns dims [w*64, w*64+64)
    const int kt   = blockIdx.x >> 1;
    const int bt   = blockIdx.x & 1;
    const int bb0  = bt * 64 + 2 * lane;

    // ---- one-time: pack W into k-pair-interleaved smem ----
    for (int i = tid; i < 12 * 512; i += GNT) {
        int gk = i >> 9, d = i & 511;        // gk = g*4 + kp
        int g = gk >> 2, kp = gk & 3;
        int k0 = kt * 8 + kp * 2;
        float lo = w_hh[((size_t)(g * H + k0)) * H + d];
        float hi = w_hh[((size_t)(g * H + k0 + 1)) * H + d];
        unsigned long long v;
        asm("mov.b64 %0, {%1, %2};" : "=l"(v)
            : "r"(__float_as_uint(lo)), "r"(__float_as_uint(hi)));
        ws64[d * 16 + gk] = v;
    }

    // ---- epilogue constants (thread owns k = kt*8 + (tid>>5), batch pair) ----
    const int kl   = tid >> 5;
    const int kg   = kt * 8 + kl;
    const int eb0  = bt * 64 + 2 * (tid & 31);
    const float wir = w_ih[kg],       wiz = w_ih[H + kg],     win = w_ih[2*H + kg];
    const float brr = b_ih[kg] + b_hh[kg];
    const float bzz = b_ih[H + kg] + b_hh[H + kg];
    const float bin = b_ih[2*H + kg], bhn = b_hh[2*H + kg];
    const int   kp_e = kl >> 1, half_e = kl & 1;

    volatile unsigned* barp = &g_bar2[bt * 32];

    __syncthreads();

    for (int t = 0; t < S; ++t) {
        const float* __restrict__ h_in  = (t & 1) ? g_hb : g_ha;
        float*       __restrict__ h_out = (t & 1) ? g_ha : g_hb;

        unsigned long long acc[3][4][2];
#pragma unroll
        for (int g = 0; g < 3; ++g)
#pragma unroll
            for (int kp = 0; kp < 4; ++kp) { acc[g][kp][0] = 0ull; acc[g][kp][1] = 0ull; }

        // ---- software-pipelined h loads: 8 chunks of 8 dims ----
        const float* __restrict__ hrow = h_in + (size_t)(w * 64) * B + bb0;
        float2 buf0[8], buf1[8];
#pragma unroll
        for (int j = 0; j < 8; ++j)
            buf0[j] = __ldcg((const float2*)(hrow + (size_t)j * B));

#pragma unroll
        for (int c = 0; c < 8; ++c) {
            const float2* cur = (c & 1) ? buf1 : buf0;
            float2*       nxt = (c & 1) ? buf0 : buf1;
            if (c < 7) {
#pragma unroll
                for (int j = 0; j < 8; ++j)
                    nxt[j] = __ldcg((const float2*)(hrow + (size_t)((c + 1) * 8 + j) * B));
            }
#pragma unroll
            for (int j = 0; j < 8; ++j) {
                const int d = w * 64 + c * 8 + j;
                const unsigned long long h0 = dup2(cur[j].x);
                const unsigned long long h1 = dup2(cur[j].y);
                const ulonglong2* wp = (const ulonglong2*)(ws64 + d * 16);
#pragma unroll
                for (int e = 0; e < 6; ++e) {
                    ulonglong2 wv = wp[e];
                    int g = e >> 1, kp = (e & 1) * 2;
                    ffma2(acc[g][kp][0],     wv.x, h0);
                    ffma2(acc[g][kp][1],     wv.x, h1);
                    ffma2(acc[g][kp + 1][0], wv.y, h0);
                    ffma2(acc[g][kp + 1][1], wv.y, h1);
                }
            }
        }

        // ---- store partials, reduce across 8 warps ----
#pragma unroll
        for (int g = 0; g < 3; ++g)
#pragma unroll
            for (int kp = 0; kp < 4; ++kp)
#pragma unroll
                for (int bj = 0; bj < 2; ++bj)
                    part[(((w * 3 + g) * 4 + kp) * 2 + bj) * 32 + lane] = acc[g][kp][bj];
        __syncthreads();

        float ga[3][2];
#pragma unroll
        for (int g = 0; g < 3; ++g)
#pragma unroll
            for (int bj = 0; bj < 2; ++bj) {
                float s = 0.0f;
#pragma unroll
                for (int ww = 0; ww < 8; ++ww)
                    s += partf[((((ww * 3 + g) * 4 + kp_e) * 2 + bj) * 32 + (tid & 31)) * 2 + half_e];
                ga[g][bj] = s;
            }

        // ---- epilogue ----
        const float2 xv   = __ldcg((const float2*)&g_feats[t * B + eb0]);
        const float2 hold = __ldcg((const float2*)&h_in[(size_t)kg * B + eb0]);
        float2 o;
        {
            float r = sigmoidf_(fmaf(xv.x, wir, brr) + ga[0][0]);
            float z = sigmoidf_(fmaf(xv.x, wiz, bzz) + ga[1][0]);
            float n = tanhf(fmaf(xv.x, win, bin) + r * (ga[2][0] + bhn));
            o.x = (1.0f - z) * n + z * hold.x;
        }
        {
            float r = sigmoidf_(fmaf(xv.y, wir, brr) + ga[0][1]);
            float z = sigmoidf_(fmaf(xv.y, wiz, bzz) + ga[1][1]);
            float n = tanhf(fmaf(xv.y, win, bin) + r * (ga[2][1] + bhn));
            o.y = (1.0f - z) * n + z * hold.y;
        }
        *(float2*)&h_out[(size_t)kg * B + eb0] = o;

        // ---- per-bt grid barrier (64 blocks), skip after last step ----
        if (t < S - 1) {
            __threadfence();
            __syncthreads();
            if (tid == 0) {
                atomicAdd((unsigned*)barp, 1u);
                const unsigned target = (unsigned)(t + 1) * 64u;
                while (*barp < target) { }
            }
            __syncthreads();
        }
    }
}

// ---------------- kernel 4: FC head ----------------
__global__ void final_kernel(const float* __restrict__ fcw,
                             const float* __restrict__ fcb,
                             float* __restrict__ out) {
    const float* __restrict__ h = g_ha;   // 512 steps -> last write in g_ha
    int b = threadIdx.x;
    float s = 0.0f;
#pragma unroll 8
    for (int d = 0; d < H; ++d) s += h[d * B + b] * fcw[d];
    out[b] = s + fcb[0];
}

// ---------------- launcher ----------------
extern "C" void kernel_launch(void* const* d_in, const int* in_sizes, int n_in,
                              void* d_out, int out_size) {
    const int*   ends = (const int*)  d_in[1];
    const float* emb  = (const float*)d_in[3];
    const float* w_ih = (const float*)d_in[4];
    const float* w_hh = (const float*)d_in[5];
    const float* b_ih = (const float*)d_in[6];
    const float* b_hh = (const float*)d_in[7];
    const float* fc_w = (const float*)d_in[8];
    const float* fc_b = (const float*)d_in[9];
    float* out = (float*)d_out;

    cudaFuncSetAttribute(gru_persist_kernel,
                         cudaFuncAttributeMaxDynamicSharedMemorySize, GRU_SMEM);

    reset_bar_kernel<<<1, 1>>>();
    zero_h_kernel<<<(H * B + 1023) / 1024, 1024>>>();
    gather_kernel<<<(S * B) / 8, 256>>>(ends, emb);
    feats_kernel<<<dim3(8, 128), 256>>>();
    gru_persist_kernel<<<NBLK, GNT, GRU_SMEM>>>(w_hh, w_ih, b_ih, b_hh);
    final_kernel<<<1, B>>>(fc_w, fc_b, out);
}

// round 6
// speedup vs baseline: 4.2835x; 1.0172x over previous
#include <cuda_runtime.h>
#include <cuda_bf16.h>
#include <math.h>

#define S   512
#define B   128
#define D   300
#define H   512
#define V   50257
#define NBLK 128
#define GNT  256   // GRU threads (8 warps)

// ---------------- device scratch ----------------
__device__ float    g_xn[(size_t)B * S * D];
__device__ float    g_feats[S * B];     // (s, b)
__device__ float    g_ha[H * B];        // dim-major h[d][b]
__device__ float    g_hb[H * B];
__device__ unsigned g_bar2[64];         // [0]: bt=0, [32]: bt=1

__global__ void reset_bar_kernel() { g_bar2[0] = 0u; g_bar2[32] = 0u; }
__global__ void zero_h_kernel() {
    int i = blockIdx.x * blockDim.x + threadIdx.x;
    if (i < H * B) g_ha[i] = 0.0f;
}

// ---------------- helpers ----------------
__device__ __forceinline__ void ffma2(unsigned long long& a,
                                      unsigned long long w,
                                      unsigned long long h) {
    asm("fma.rn.f32x2 %0, %1, %2, %0;" : "+l"(a) : "l"(w), "l"(h));
}
__device__ __forceinline__ unsigned long long dup2(float v) {
    unsigned long long r; unsigned u = __float_as_uint(v);
    asm("mov.b64 %0, {%1, %1};" : "=l"(r) : "r"(u));
    return r;
}
__device__ __forceinline__ float2 unpk(unsigned long long v) {
    unsigned lo, hi;
    asm("mov.b64 {%0, %1}, %2;" : "=r"(lo), "=r"(hi) : "l"(v));
    return make_float2(__uint_as_float(lo), __uint_as_float(hi));
}
__device__ __forceinline__ float sigmoidf_(float x) { return 1.0f / (1.0f + expf(-x)); }

// ---------------- kernel 1: gather + normalize ----------------
__global__ void gather_kernel(const int* __restrict__ ends,
                              const float* __restrict__ emb) {
    int w    = (blockIdx.x * blockDim.x + threadIdx.x) >> 5;
    int lane = threadIdx.x & 31;
    if (w >= S * B) return;
    int s = w >> 7, b = w & 127;
    const float* row = emb + (size_t)ends[s * B + b] * D;
    float v[10]; float ss = 0.0f;
#pragma unroll
    for (int i = 0; i < 10; ++i) {
        int d = lane + 32 * i;
        v[i] = (d < D) ? row[d] : 0.0f;
        ss += v[i] * v[i];
    }
#pragma unroll
    for (int m = 16; m; m >>= 1) ss += __shfl_xor_sync(0xffffffffu, ss, m);
    float inv = 1.0f / fmaxf(sqrtf(ss), 1e-8f);
    float* dst = g_xn + ((size_t)b * S + s) * D;
#pragma unroll
    for (int i = 0; i < 10; ++i) {
        int d = lane + 32 * i;
        if (d < D) dst[d] = v[i] * inv;
    }
}

// ---------------- kernel 2: causal max cosine sims ----------------
// A tiles hoisted to smem once (invariant over jt); B tile double-buffered.
#define FP 68
#define FEATS_F (12 * 25 * FP + 2 * 25 * FP)
#define FEATS_SMEM (FEATS_F * 4)

__global__ void feats_kernel() {
    extern __shared__ float fsm[];
    float* At = fsm;                   // [(kc*25+kk)*FP + row]
    float* Bt = fsm + 12 * 25 * FP;    // [buf*25*FP + kk*FP + row]

    const int it = blockIdx.x, b = blockIdx.y;
    const float* Xb = g_xn + (size_t)b * S * D;
    const int tid = threadIdx.x, tx = tid & 15, ty = tid >> 4;
    const int wa = tid >> 5, lane = tid & 31;
    const int i0 = it * 64;

    // one-time A fill: 12 kc-subtiles, transposed [kk][row]
    if (lane < 25) {
        for (int kc = 0; kc < 12; ++kc)
#pragma unroll
            for (int i = 0; i < 8; ++i) {
                int row = wa * 8 + i;
                At[(kc * 25 + lane) * FP + row] =
                    Xb[(size_t)(i0 + row) * D + kc * 25 + lane];
            }
    }
    float rowmax[4] = { -INFINITY, -INFINITY, -INFINITY, -INFINITY };
    __syncthreads();

    for (int jt = 0; jt <= it; ++jt) {
        const int j0 = jt * 64;
        unsigned long long acc2[4][2];
#pragma unroll
        for (int r = 0; r < 4; ++r) { acc2[r][0] = 0ull; acc2[r][1] = 0ull; }

        // prime B buffer 0 with kc=0
        if (lane < 25) {
#pragma unroll
            for (int i = 0; i < 8; ++i) {
                int row = wa * 8 + i;
                Bt[lane * FP + row] = Xb[(size_t)(j0 + row) * D + lane];
            }
        }
        __syncthreads();

        for (int kc = 0; kc < 12; ++kc) {
            const float* Bc = Bt + (kc & 1) * (25 * FP);
            if (kc < 11 && lane < 25) {
                float* Bn = Bt + ((kc + 1) & 1) * (25 * FP);
#pragma unroll
                for (int i = 0; i < 8; ++i) {
                    int row = wa * 8 + i;
                    Bn[lane * FP + row] =
                        Xb[(size_t)(j0 + row) * D + (kc + 1) * 25 + lane];
                }
            }
            const float* Ac = At + kc * 25 * FP;
#pragma unroll
            for (int kk = 0; kk < 25; ++kk) {
                const float4 a4 = *(const float4*)(Ac + kk * FP + ty * 4);
                const ulonglong2 cp = *(const ulonglong2*)(Bc + kk * FP + tx * 4);
                const unsigned long long a0 = dup2(a4.x), a1 = dup2(a4.y);
                const unsigned long long a2 = dup2(a4.z), a3 = dup2(a4.w);
                ffma2(acc2[0][0], a0, cp.x); ffma2(acc2[0][1], a0, cp.y);
                ffma2(acc2[1][0], a1, cp.x); ffma2(acc2[1][1], a1, cp.y);
                ffma2(acc2[2][0], a2, cp.x); ffma2(acc2[2][1], a2, cp.y);
                ffma2(acc2[3][0], a3, cp.x); ffma2(acc2[3][1], a3, cp.y);
            }
            __syncthreads();
        }
        // causal-masked running max
#pragma unroll
        for (int r = 0; r < 4; ++r) {
            int i = i0 + ty * 4 + r;
            float2 v01 = unpk(acc2[r][0]);
            float2 v23 = unpk(acc2[r][1]);
            int j = j0 + tx * 4;
            if (j + 0 < i) rowmax[r] = fmaxf(rowmax[r], v01.x);
            if (j + 1 < i) rowmax[r] = fmaxf(rowmax[r], v01.y);
            if (j + 2 < i) rowmax[r] = fmaxf(rowmax[r], v23.x);
            if (j + 3 < i) rowmax[r] = fmaxf(rowmax[r], v23.y);
        }
    }
#pragma unroll
    for (int m = 8; m; m >>= 1)
#pragma unroll
        for (int r = 0; r < 4; ++r)
            rowmax[r] = fmaxf(rowmax[r], __shfl_xor_sync(0xffffffffu, rowmax[r], m));
    if (tx == 0)
#pragma unroll
        for (int r = 0; r < 4; ++r) {
            int i = i0 + ty * 4 + r;
            g_feats[i * B + b] = (i == 0) ? 0.0f : rowmax[r];
        }
}

// ---------------- kernel 3: persistent GRU ----------------
// block = 8 k (kt) x 64 b (bt); 8 warps split 512 dims.
// lane: kh = lane>>4 (k-half), bq = lane&15 (batch quad -> float4 h loads).
#define WS_U64   (512 * 16)
#define PART_U64 (8 * 3 * 4 * 4 * 16)
#define GRU_SMEM ((WS_U64 + PART_U64) * 8)

__global__ void __launch_bounds__(GNT, 1)
gru_persist_kernel(const float* __restrict__ w_hh,
                   const float* __restrict__ w_ih,
                   const float* __restrict__ b_ih,
                   const float* __restrict__ b_hh) {
    extern __shared__ unsigned long long sm64[];
    unsigned long long* ws64 = sm64;            // [d*16 + g*4 + kpg]
    unsigned long long* part = sm64 + WS_U64;

    const int tid  = threadIdx.x;
    const int lane = tid & 31;
    const int w    = tid >> 5;           // warp owns dims [w*64, w*64+64)
    const int kt   = blockIdx.x >> 1;
    const int bt   = blockIdx.x & 1;
    const int kh   = lane >> 4;          // k-half 0/1
    const int bq   = lane & 15;          // batch quad

    // ---- one-time: pack W as k-pair f32x2 ----
    for (int i = tid; i < 12 * 512; i += GNT) {
        int gk = i >> 9, d = i & 511;        // gk = g*4 + kpg
        int g = gk >> 2, kpg = gk & 3;
        int k0 = kt * 8 + kpg * 2;
        float lo = w_hh[((size_t)(g * H + k0)) * H + d];
        float hi = w_hh[((size_t)(g * H + k0 + 1)) * H + d];
        unsigned long long v;
        asm("mov.b64 %0, {%1, %2};" : "=l"(v)
            : "r"(__float_as_uint(lo)), "r"(__float_as_uint(hi)));
        ws64[d * 16 + gk] = v;
    }

    // ---- epilogue constants: thread owns k-pair kpl, batch be ----
    const int kpl  = tid >> 6;           // 0..3
    const int bl   = tid & 63;
    const int k0   = kt * 8 + kpl * 2, k1 = k0 + 1;
    const int be   = bt * 64 + bl;
    const int bi_e = bl & 3, bq_e = bl >> 2;
    const float wir0 = w_ih[k0],         wir1 = w_ih[k1];
    const float wiz0 = w_ih[H + k0],     wiz1 = w_ih[H + k1];
    const float win0 = w_ih[2*H + k0],   win1 = w_ih[2*H + k1];
    const float brr0 = b_ih[k0] + b_hh[k0],         brr1 = b_ih[k1] + b_hh[k1];
    const float bzz0 = b_ih[H + k0] + b_hh[H + k0], bzz1 = b_ih[H + k1] + b_hh[H + k1];
    const float bin0 = b_ih[2*H + k0],   bin1 = b_ih[2*H + k1];
    const float bhn0 = b_hh[2*H + k0],   bhn1 = b_hh[2*H + k1];

    unsigned* barp = &g_bar2[bt * 32];

    __syncthreads();

    for (int t = 0; t < S; ++t) {
        const float* __restrict__ h_in  = (t & 1) ? g_hb : g_ha;
        float*       __restrict__ h_out = (t & 1) ? g_ha : g_hb;

        unsigned long long acc[3][2][4];
#pragma unroll
        for (int g = 0; g < 3; ++g)
#pragma unroll
            for (int kp = 0; kp < 2; ++kp)
#pragma unroll
                for (int bi = 0; bi < 4; ++bi) acc[g][kp][bi] = 0ull;

        // ---- main loop: float4 h loads (lanes 16-31 dedup with 0-15) ----
        const float* __restrict__ hrow =
            h_in + (size_t)(w * 64) * B + bt * 64 + bq * 4;
        float4 buf[2][4];
#pragma unroll
        for (int j = 0; j < 4; ++j)
            buf[0][j] = __ldcg((const float4*)(hrow + (size_t)j * B));

#pragma unroll
        for (int c = 0; c < 16; ++c) {
            const float4* cur = buf[c & 1];
            float4*       nxt = buf[(c + 1) & 1];
            if (c < 15) {
#pragma unroll
                for (int j = 0; j < 4; ++j)
                    nxt[j] = __ldcg((const float4*)(hrow + (size_t)((c + 1) * 4 + j) * B));
            }
#pragma unroll
            for (int j = 0; j < 4; ++j) {
                const int d = w * 64 + c * 4 + j;
                const unsigned long long h0 = dup2(cur[j].x);
                const unsigned long long h1 = dup2(cur[j].y);
                const unsigned long long h2 = dup2(cur[j].z);
                const unsigned long long h3 = dup2(cur[j].w);
                const ulonglong2* wp = (const ulonglong2*)(ws64 + d * 16 + kh * 2);
#pragma unroll
                for (int g = 0; g < 3; ++g) {
                    const ulonglong2 wv = wp[g * 2];
                    ffma2(acc[g][0][0], wv.x, h0); ffma2(acc[g][0][1], wv.x, h1);
                    ffma2(acc[g][0][2], wv.x, h2); ffma2(acc[g][0][3], wv.x, h3);
                    ffma2(acc[g][1][0], wv.y, h0); ffma2(acc[g][1][1], wv.y, h1);
                    ffma2(acc[g][1][2], wv.y, h2); ffma2(acc[g][1][3], wv.y, h3);
                }
            }
        }

        // ---- partials ----
#pragma unroll
        for (int g = 0; g < 3; ++g)
#pragma unroll
            for (int kp = 0; kp < 2; ++kp)
#pragma unroll
                for (int bi = 0; bi < 4; ++bi)
                    part[(((w * 3 + g) * 4 + (kh * 2 + kp)) * 4 + bi) * 16 + bq] =
                        acc[g][kp][bi];
        __syncthreads();

        // ---- reduce across 8 warps with add.f32x2 ----
        unsigned long long ga2[3];
#pragma unroll
        for (int g = 0; g < 3; ++g) {
            unsigned long long s = part[((g * 4 + kpl) * 4 + bi_e) * 16 + bq_e];
#pragma unroll
            for (int ww = 1; ww < 8; ++ww) {
                unsigned long long p =
                    part[(((ww * 3 + g) * 4 + kpl) * 4 + bi_e) * 16 + bq_e];
                asm("add.rn.f32x2 %0, %0, %1;" : "+l"(s) : "l"(p));
            }
            ga2[g] = s;
        }
        const float2 gr = unpk(ga2[0]);
        const float2 gz = unpk(ga2[1]);
        const float2 gn = unpk(ga2[2]);

        // ---- epilogue ----
        const float x     = __ldcg(&g_feats[t * B + be]);
        const float hold0 = __ldcg(&h_in[(size_t)k0 * B + be]);
        const float hold1 = __ldcg(&h_in[(size_t)k1 * B + be]);
        {
            float r = sigmoidf_(fmaf(x, wir0, brr0) + gr.x);
            float z = sigmoidf_(fmaf(x, wiz0, bzz0) + gz.x);
            float n = tanhf(fmaf(x, win0, bin0) + r * (gn.x + bhn0));
            h_out[(size_t)k0 * B + be] = (1.0f - z) * n + z * hold0;
        }
        {
            float r = sigmoidf_(fmaf(x, wir1, brr1) + gr.y);
            float z = sigmoidf_(fmaf(x, wiz1, bzz1) + gz.y);
            float n = tanhf(fmaf(x, win1, bin1) + r * (gn.y + bhn1));
            h_out[(size_t)k1 * B + be] = (1.0f - z) * n + z * hold1;
        }

        // ---- per-bt grid barrier: bar.sync + red.release / ld.acquire ----
        if (t < S - 1) {
            __syncthreads();
            if (tid == 0) {
                unsigned one = 1u;
                asm volatile("red.release.gpu.global.add.u32 [%0], %1;"
                             :: "l"(barp), "r"(one) : "memory");
                const unsigned target = (unsigned)(t + 1) * 64u;
                unsigned v;
                do {
                    asm volatile("ld.acquire.gpu.global.u32 %0, [%1];"
                                 : "=r"(v) : "l"(barp) : "memory");
                } while (v < target);
            }
            __syncthreads();
        }
    }
}

// ---------------- kernel 4: FC head ----------------
__global__ void final_kernel(const float* __restrict__ fcw,
                             const float* __restrict__ fcb,
                             float* __restrict__ out) {
    const float* __restrict__ h = g_ha;   // 512 steps -> last write in g_ha
    int b = threadIdx.x;
    float s = 0.0f;
#pragma unroll 8
    for (int d = 0; d < H; ++d) s += h[d * B + b] * fcw[d];
    out[b] = s + fcb[0];
}

// ---------------- launcher ----------------
extern "C" void kernel_launch(void* const* d_in, const int* in_sizes, int n_in,
                              void* d_out, int out_size) {
    const int*   ends = (const int*)  d_in[1];
    const float* emb  = (const float*)d_in[3];
    const float* w_ih = (const float*)d_in[4];
    const float* w_hh = (const float*)d_in[5];
    const float* b_ih = (const float*)d_in[6];
    const float* b_hh = (const float*)d_in[7];
    const float* fc_w = (const float*)d_in[8];
    const float* fc_b = (const float*)d_in[9];
    float* out = (float*)d_out;

    cudaFuncSetAttribute(gru_persist_kernel,
                         cudaFuncAttributeMaxDynamicSharedMemorySize, GRU_SMEM);
    cudaFuncSetAttribute(feats_kernel,
                         cudaFuncAttributeMaxDynamicSharedMemorySize, FEATS_SMEM);

    reset_bar_kernel<<<1, 1>>>();
    zero_h_kernel<<<(H * B + 1023) / 1024, 1024>>>();
    gather_kernel<<<(S * B) / 8, 256>>>(ends, emb);
    feats_kernel<<<dim3(8, 128), 256, FEATS_SMEM>>>();
    gru_persist_kernel<<<NBLK, GNT, GRU_SMEM>>>(w_hh, w_ih, b_ih, b_hh);
    final_kernel<<<1, B>>>(fc_w, fc_b, out);
}